// round 14
// baseline (speedup 1.0000x reference)
#include <cuda_runtime.h>
#include <cuda_bf16.h>
#include <cstdint>

// ============================================================================
// Problem constants
// ============================================================================
#define Bn 128
#define Sn 2048
#define Hn 512
#define An 512
#define BSn (Bn * Sn)            // 262144 rows
#define M_TILE 128
#define N_TILES (BSn / M_TILE)   // 2048 CTAs (16 per batch)
#define KC 64                    // K per chunk
#define NC 128                   // N per chunk
#define NKC (Hn / KC)            // 8
#define NNC (An / NC)            // 4
#define NITER (NKC * NNC)        // 32
#define THREADS 512

// ============================================================================
// Device scratch
// ============================================================================
__device__ float g_vu[BSn];                       // 1 MB
__device__ __nv_bfloat16 g_wt[An * Hn];           // 512 KB, Wt[a][h] = W[h][a]
__device__ float g_part[N_TILES * Hn];            // 4 MB partial pooled vectors
__device__ float g_m[N_TILES];                    // per-tile local max
__device__ float g_s[N_TILES];                    // per-tile local expsum

// ============================================================================
// Helpers (baseline PTX only — no 'a'-suffix features)
// ============================================================================
__device__ __forceinline__ uint32_t smem_to_u32(const void* p) {
    uint32_t a;
    asm("{ .reg .u64 t; cvta.to.shared.u64 t, %1; cvt.u32.u64 %0, t; }" : "=r"(a) : "l"(p));
    return a;
}
__device__ __forceinline__ void ldsm_x4(uint32_t addr, uint32_t r[4]) {
    asm volatile("ldmatrix.sync.aligned.m8n8.x4.shared.b16 {%0,%1,%2,%3}, [%4];"
        : "=r"(r[0]), "=r"(r[1]), "=r"(r[2]), "=r"(r[3]) : "r"(addr));
}
__device__ __forceinline__ void mma16816(float d[4], const uint32_t a[4],
                                         const uint32_t b[2]) {
    asm volatile("mma.sync.aligned.m16n8k16.row.col.f32.bf16.bf16.f32 "
        "{%0,%1,%2,%3}, {%4,%5,%6,%7}, {%8,%9}, {%0,%1,%2,%3};"
        : "+f"(d[0]), "+f"(d[1]), "+f"(d[2]), "+f"(d[3])
        : "r"(a[0]), "r"(a[1]), "r"(a[2]), "r"(a[3]), "r"(b[0]), "r"(b[1]));
}
__device__ __forceinline__ void cp_async16(uint32_t dst, const void* src) {
    asm volatile("cp.async.cg.shared.global [%0], [%1], 16;" :: "r"(dst), "l"(src));
}
__device__ __forceinline__ void cp_commit() {
    asm volatile("cp.async.commit_group;" ::: "memory");
}
__device__ __forceinline__ float fast_tanh(float x) {
    float y;
    asm("tanh.approx.f32 %0, %1;" : "=f"(y) : "f"(x));
    return y;
}

// ============================================================================
// SMEM layout for pass1 (dynamic) — occ 1, M=128 (R10-proven config)
// ============================================================================
// x resident tile: 128 rows x 1024B (512 bf16), XOR-swizzled at 16B granule
#define OFF_XT   0
#define XT_BYTES (128 * 1024)            // 131072
// W chunk TRIPLE buffer: 128 n-rows x 144B (64 bf16 + 8 pad)
#define OFF_W0   XT_BYTES
#define W_ROWB   144
#define W_BUF    (128 * W_ROWB)          // 18432
// fp32 x staging: 128 rows x 64 floats = 32KB (single buffer, distance-1)
#define OFF_STG  (OFF_W0 + 3 * W_BUF)    // 186368
#define STG_BYTES 32768
#define OFF_B    (OFF_STG + STG_BYTES)   // 219136
#define OFF_U    (OFF_B + 2048)          // 221184
#define OFF_VU   (OFF_U + 2048)          // 223232 (128 floats)
#define OFF_RED  (OFF_VU + 512)          // 223744 (reduction scratch)
#define OFF_SW   (OFF_RED + 128)         // 223872 (128 softmax weights)
#define SMEM_TOTAL (OFF_SW + 512)        // 224384

// swizzled x address for (row, k-element)
__device__ __forceinline__ uint32_t xt_addr(uint32_t sb, int row, int k) {
    uint32_t unit = ((uint32_t)k >> 3) ^ ((uint32_t)row & 7);
    return sb + OFF_XT + (uint32_t)row * 1024 + (unit << 4) + (((uint32_t)k * 2) & 15);
}

// ============================================================================
// Kernel 0: W transpose + bf16 convert via SMEM-tiled transpose.
// 32x32 tiles -> 256 blocks (fills the chip), coalesced both directions.
// ============================================================================
__global__ void wprep_kernel(const float* __restrict__ w) {
    __shared__ __nv_bfloat16 t[32][33];          // +1 pad: conflict-free
    const int bh = (blockIdx.x >> 4) * 32;       // h tile origin (16 tiles)
    const int ba = (blockIdx.x & 15) * 32;       // a tile origin (16 tiles)
    #pragma unroll
    for (int i = 0; i < 4; i++) {
        const int idx = i * 256 + threadIdx.x;   // 0..1023
        const int h = idx >> 5, a = idx & 31;    // read coalesced in a
        t[a][h] = __float2bfloat16(w[(size_t)(bh + h) * An + ba + a]);
    }
    __syncthreads();
    #pragma unroll
    for (int i = 0; i < 4; i++) {
        const int idx = i * 256 + threadIdx.x;
        const int a = idx >> 5, h = idx & 31;    // write coalesced in h
        g_wt[(size_t)(ba + a) * Hn + bh + h] = t[a][h];
    }
}

// ============================================================================
// Prefetch helpers — each ALWAYS commits a group (uniform accounting).
// 512 threads.
// ============================================================================
__device__ __forceinline__ void prefetch_W(uint32_t sb, int jt, int tid) {
    if (jt < NITER) {
        const int nn = jt >> 3, nk = jt & 7;
        const uint32_t dbase = sb + OFF_W0 + (jt % 3) * W_BUF;
        const int idx0 = tid * 2;
        #pragma unroll
        for (int i = 0; i < 2; i++) {
            const int idx = idx0 + i;                 // 1024 16B units
            const int r = idx >> 3, un = idx & 7;
            const __nv_bfloat16* src =
                g_wt + (size_t)(nn * NC + r) * Hn + nk * KC + un * 8;
            cp_async16(dbase + r * W_ROWB + un * 16, src);
        }
    }
    cp_commit();
}

__device__ __forceinline__ void prefetch_X(uint32_t sb, const float* __restrict__ x,
                                           size_t row0, int kc, int tid) {
    if (kc < NKC) {
        #pragma unroll
        for (int i = 0; i < 4; i++) {
            const int idx = tid + i * THREADS;        // 2048 16B units
            const int r = idx >> 4, un = idx & 15;    // row, float4-index
            const float* src = x + (row0 + r) * Hn + kc * KC + un * 4;
            cp_async16(sb + OFF_STG + r * 256 + un * 16, src);
        }
    }
    cp_commit();
}

// Convert staged fp32 chunk c -> swizzled bf16 resident tile (thread-local
// mapping matches prefetch_X, so staging reuse after this call is race-free).
__device__ __forceinline__ void convert_X(uint32_t sb, char* smem, int c, int tid) {
    #pragma unroll
    for (int i = 0; i < 4; i++) {
        const int idx = tid + i * THREADS;
        const int r = idx >> 4;
        const int c4 = idx & 15;
        const float4 v = *(const float4*)(smem + OFF_STG + r * 256 + c4 * 16);
        __nv_bfloat162 p0 = __floats2bfloat162_rn(v.x, v.y);
        __nv_bfloat162 p1 = __floats2bfloat162_rn(v.z, v.w);
        uint2 st;
        st.x = *reinterpret_cast<const uint32_t*>(&p0);
        st.y = *reinterpret_cast<const uint32_t*>(&p1);
        const int k = c * KC + c4 * 4;
        *(uint2*)(smem + (xt_addr(sb, r, k) - sb)) = st;
    }
}

// ============================================================================
// Kernel 1: fused GEMM(tanh, u-dot) -> g_vu, then per-tile local softmax
// weights + fp32 partial pooling.  512 threads (16 warps: 4x4 warp tiling).
// Conversion runs one chunk AHEAD of consumption -> no second barrier.
// ============================================================================
__global__ void __launch_bounds__(THREADS, 1)
pass1_kernel(const float* __restrict__ x, const float* __restrict__ bo,
             const float* __restrict__ uo) {
    extern __shared__ char smem[];
    const uint32_t sb = smem_to_u32(smem);
    const int tid = threadIdx.x;
    const int lane = tid & 31;
    const int wid = tid >> 5;
    const int warp_m = wid & 3;           // 4 m-tiles of 32 rows
    const int warp_n = wid >> 2;          // 4 n-tiles of 32 cols
    const size_t row0 = (size_t)blockIdx.x * M_TILE;

    float* s_b   = (float*)(smem + OFF_B);
    float* s_u   = (float*)(smem + OFF_U);
    float* s_vu  = (float*)(smem + OFF_VU);
    float* s_red = (float*)(smem + OFF_RED);
    float* s_w   = (float*)(smem + OFF_SW);
    const float inv_sqrtA = 0.04419417382415922f;   // 1/sqrt(512)
    for (int i = tid; i < An; i += THREADS) {
        s_b[i] = bo[i];
        s_u[i] = uo[i] * inv_sqrtA;
    }
    if (tid < 128) s_vu[tid] = 0.0f;

    // Prologue: W0, X0 -> drain -> convert chunk 0 -> stage X1, W1.
    prefetch_W(sb, 0, tid);
    prefetch_X(sb, x, row0, 0, tid);
    asm volatile("cp.async.wait_group 0;" ::: "memory");
    __syncthreads();
    convert_X(sb, smem, 0, tid);
    prefetch_X(sb, x, row0, 1, tid);
    prefetch_W(sb, 1, tid);

    float acc[2][4][4];

    #pragma unroll 1
    for (int it = 0; it < NITER; it++) {
        const int nc = it >> 3;
        const int kc = it & 7;

        // Completes all but newest group: guarantees W(it) and staged X(kc+1)
        // have landed; also makes last iteration's conversion STS visible.
        asm volatile("cp.async.wait_group 1;" ::: "memory");
        __syncthreads();

        // Convert NEXT chunk (consumed next iteration — its visibility is
        // covered by the next iteration's barrier; no extra sync needed).
        if (nc == 0 && kc < NKC - 1)
            convert_X(sb, smem, kc + 1, tid);

        // Issue next prefetches (staging reuse is thread-local-safe).
        prefetch_X(sb, x, row0, (nc == 0) ? (kc + 2) : NKC, tid);
        prefetch_W(sb, it + 2, tid);

        if (kc == 0) {
            #pragma unroll
            for (int mi = 0; mi < 2; mi++)
                #pragma unroll
                for (int ni = 0; ni < 4; ni++)
                    #pragma unroll
                    for (int j = 0; j < 4; j++) acc[mi][ni][j] = 0.0f;
        }

        // ---- compute this (nc, kc) chunk: 4 k-steps of 16 ----
        const uint32_t wb = sb + OFF_W0 + (it % 3) * W_BUF;
        #pragma unroll
        for (int ks = 0; ks < 4; ks++) {
            uint32_t afr[2][4];
            #pragma unroll
            for (int mi = 0; mi < 2; mi++) {
                const int row = warp_m * 32 + mi * 16 + (lane & 15);
                const int k = kc * KC + ks * 16 + (lane >> 4) * 8;
                ldsm_x4(xt_addr(sb, row, k), afr[mi]);
            }
            uint32_t bfr[4][2];
            #pragma unroll
            for (int g = 0; g < 2; g++) {
                const int n = warp_n * 32 + g * 16 + (lane & 15);
                uint32_t r4[4];
                ldsm_x4(wb + n * W_ROWB + ks * 32 + (lane >> 4) * 16, r4);
                bfr[2 * g][0] = r4[0]; bfr[2 * g][1] = r4[2];
                bfr[2 * g + 1][0] = r4[1]; bfr[2 * g + 1][1] = r4[3];
            }
            #pragma unroll
            for (int mi = 0; mi < 2; mi++)
                #pragma unroll
                for (int ni = 0; ni < 4; ni++)
                    mma16816(acc[mi][ni], afr[mi], bfr[ni]);
        }

        // ---- epilogue after full K sweep for this N-chunk ----
        if (kc == 7) {
            float pv[4] = {0.f, 0.f, 0.f, 0.f};   // [mi*2 + hi]
            #pragma unroll
            for (int mi = 0; mi < 2; mi++) {
                #pragma unroll
                for (int ni = 0; ni < 4; ni++) {
                    const int a0 = nc * NC + warp_n * 32 + ni * 8 + (lane & 3) * 2;
                    const float b0 = s_b[a0],     b1 = s_b[a0 + 1];
                    const float u0 = s_u[a0],     u1 = s_u[a0 + 1];
                    pv[mi * 2 + 0] += fast_tanh(acc[mi][ni][0] + b0) * u0
                                    + fast_tanh(acc[mi][ni][1] + b1) * u1;
                    pv[mi * 2 + 1] += fast_tanh(acc[mi][ni][2] + b0) * u0
                                    + fast_tanh(acc[mi][ni][3] + b1) * u1;
                }
            }
            #pragma unroll
            for (int j = 0; j < 4; j++) {
                float v = pv[j];
                v += __shfl_xor_sync(0xffffffffu, v, 1);
                v += __shfl_xor_sync(0xffffffffu, v, 2);
                if ((lane & 3) == 0) {
                    const int row = warp_m * 32 + (j >> 1) * 16 + (lane >> 2) + (j & 1) * 8;
                    atomicAdd(&s_vu[row], v);
                }
            }
        }
    }

    __syncthreads();
    if (tid < 128) g_vu[row0 + tid] = s_vu[tid];

    // ============== local softmax weights + fp32 partial pooling ==========
    if (wid == 0) {
        float a0 = fmaxf(s_vu[lane], s_vu[lane + 32]);
        float a1 = fmaxf(s_vu[lane + 64], s_vu[lane + 96]);
        float m = fmaxf(a0, a1);
        #pragma unroll
        for (int off = 16; off > 0; off >>= 1)
            m = fmaxf(m, __shfl_xor_sync(0xffffffffu, m, off));
        if (lane == 0) s_red[0] = m;
    }
    __syncthreads();
    const float lm = s_red[0];

    if (tid < 128) {
        const float w = expf(s_vu[tid] - lm);
        s_w[tid] = w;
        float sw = w;
        #pragma unroll
        for (int off = 16; off > 0; off >>= 1)
            sw += __shfl_xor_sync(0xffffffffu, sw, off);
        if (lane == 0) s_red[1 + wid] = sw;
    }
    __syncthreads();

    // partial pooled vector: P[h] = sum_r w_r * x[r][h] (fp32, direct LDG)
    // 512 threads: one column each. MLP=32 batches, 4 accumulators.
    const float* xb = x + row0 * Hn + tid;
    float a0 = 0.f, a1 = 0.f, a2 = 0.f, a3 = 0.f;
    #pragma unroll 1
    for (int rb = 0; rb < 128; rb += 32) {
        float v[32];
        #pragma unroll
        for (int i = 0; i < 32; i++)
            v[i] = xb[(size_t)(rb + i) * Hn];
        #pragma unroll
        for (int i = 0; i < 32; i += 4) {
            a0 = fmaf(s_w[rb + i + 0], v[i + 0], a0);
            a1 = fmaf(s_w[rb + i + 1], v[i + 1], a1);
            a2 = fmaf(s_w[rb + i + 2], v[i + 2], a2);
            a3 = fmaf(s_w[rb + i + 3], v[i + 3], a3);
        }
    }
    g_part[(size_t)blockIdx.x * Hn + tid] = (a0 + a1) + (a2 + a3);
    if (tid == 0) {
        g_m[blockIdx.x] = lm;
        g_s[blockIdx.x] = s_red[1] + s_red[2] + s_red[3] + s_red[4];
    }
}

// ============================================================================
// Kernel 2 (merged tail): per-batch softmax -> alphas + combine -> out.
// ============================================================================
__global__ void __launch_bounds__(512)
finish_kernel(float* __restrict__ out, float* __restrict__ alphas) {
    const int b = blockIdx.x;
    const int tid = threadIdx.x;
    const int w = tid >> 5, l = tid & 31;
    const float* vu = g_vu + (size_t)b * Sn;

    __shared__ float redm[16];
    __shared__ float reds[16];
    __shared__ float scoef[16];
    __shared__ float sZ;

    // ---- softmax over S=2048 (4 values/thread) ----
    float v[4];
    #pragma unroll
    for (int j = 0; j < 4; j++) v[j] = vu[tid + j * 512];

    float m = fmaxf(fmaxf(v[0], v[1]), fmaxf(v[2], v[3]));
    #pragma unroll
    for (int off = 16; off > 0; off >>= 1)
        m = fmaxf(m, __shfl_xor_sync(0xffffffffu, m, off));
    if (l == 0) redm[w] = m;
    __syncthreads();
    float gm = redm[0];
    #pragma unroll
    for (int i = 1; i < 16; i++) gm = fmaxf(gm, redm[i]);

    float e[4];
    float s = 0.0f;
    #pragma unroll
    for (int j = 0; j < 4; j++) { e[j] = expf(v[j] - gm); s += e[j]; }
    #pragma unroll
    for (int off = 16; off > 0; off >>= 1)
        s += __shfl_xor_sync(0xffffffffu, s, off);
    if (l == 0) reds[w] = s;

    // ---- combine coefficients (independent of softmax reductions) ----
    if (tid == 256) {
        float mm[16], ss[16];
        #pragma unroll
        for (int i = 0; i < 16; i++) { mm[i] = g_m[b * 16 + i]; ss[i] = g_s[b * 16 + i]; }
        float M = mm[0];
        #pragma unroll
        for (int i = 1; i < 16; i++) M = fmaxf(M, mm[i]);
        float Z = 0.0f;
        #pragma unroll
        for (int i = 0; i < 16; i++) {
            const float c = expf(mm[i] - M);
            scoef[i] = c;
            Z += c * ss[i];
        }
        sZ = Z + 1e-10f;
    }
    __syncthreads();

    float gs = 0.0f;
    #pragma unroll
    for (int i = 0; i < 16; i++) gs += reds[i];
    const float inv = 1.0f / (gs + 1e-10f);

    float* ao = alphas + (size_t)b * Sn;
    #pragma unroll
    for (int j = 0; j < 4; j++) ao[tid + j * 512] = e[j] * inv;

    // ---- combine: out[b][h] ----
    float acc = 0.0f;
    const float* pp = g_part + (size_t)b * 16 * Hn + tid;
    #pragma unroll
    for (int i = 0; i < 16; i++)
        acc = fmaf(scoef[i], pp[(size_t)i * Hn], acc);
    out[(size_t)b * Hn + tid] = acc / sZ;
}

// ============================================================================
// Launch
// ============================================================================
extern "C" void kernel_launch(void* const* d_in, const int* in_sizes, int n_in,
                              void* d_out, int out_size) {
    const float* x  = (const float*)d_in[0];   // [B,S,H]
    const float* w  = (const float*)d_in[1];   // [H,A]
    const float* bo = (const float*)d_in[2];   // [A]
    const float* uo = (const float*)d_in[3];   // [A]
    float* out = (float*)d_out;                // [B*H] output then [B*S] alphas
    float* alphas = out + (size_t)Bn * Hn;

    cudaFuncSetAttribute(pass1_kernel, cudaFuncAttributeMaxDynamicSharedMemorySize,
                         SMEM_TOTAL);

    wprep_kernel<<<256, 256>>>(w);
    pass1_kernel<<<N_TILES, THREADS, SMEM_TOTAL>>>(x, bo, uo);
    finish_kernel<<<Bn, 512>>>(out, alphas);
}

// round 15
// speedup vs baseline: 1.5005x; 1.5005x over previous
#include <cuda_runtime.h>
#include <cuda_bf16.h>
#include <cstdint>

// ============================================================================
// Problem constants
// ============================================================================
#define Bn 128
#define Sn 2048
#define Hn 512
#define An 512
#define BSn (Bn * Sn)            // 262144 rows
#define M_TILE 128
#define N_TILES (BSn / M_TILE)   // 2048 CTAs (16 per batch)
#define KC 64                    // K per chunk
#define NC 128                   // N per chunk
#define NKC (Hn / KC)            // 8
#define NNC (An / NC)            // 4
#define NITER (NKC * NNC)        // 32
#define THREADS 512

// ============================================================================
// Device scratch
// ============================================================================
__device__ float g_vu[BSn];                       // 1 MB
__device__ __nv_bfloat16 g_wt[An * Hn];           // 512 KB, Wt[a][h] = W[h][a]
__device__ float g_part[N_TILES * Hn];            // 4 MB partial pooled vectors
__device__ float g_m[N_TILES];                    // per-tile local max
__device__ float g_s[N_TILES];                    // per-tile local expsum

// ============================================================================
// Helpers (baseline PTX only — no 'a'-suffix features)
// ============================================================================
__device__ __forceinline__ uint32_t smem_to_u32(const void* p) {
    uint32_t a;
    asm("{ .reg .u64 t; cvta.to.shared.u64 t, %1; cvt.u32.u64 %0, t; }" : "=r"(a) : "l"(p));
    return a;
}
__device__ __forceinline__ void ldsm_x4(uint32_t addr, uint32_t r[4]) {
    asm volatile("ldmatrix.sync.aligned.m8n8.x4.shared.b16 {%0,%1,%2,%3}, [%4];"
        : "=r"(r[0]), "=r"(r[1]), "=r"(r[2]), "=r"(r[3]) : "r"(addr));
}
__device__ __forceinline__ void mma16816(float d[4], const uint32_t a[4],
                                         const uint32_t b[2]) {
    asm volatile("mma.sync.aligned.m16n8k16.row.col.f32.bf16.bf16.f32 "
        "{%0,%1,%2,%3}, {%4,%5,%6,%7}, {%8,%9}, {%0,%1,%2,%3};"
        : "+f"(d[0]), "+f"(d[1]), "+f"(d[2]), "+f"(d[3])
        : "r"(a[0]), "r"(a[1]), "r"(a[2]), "r"(a[3]), "r"(b[0]), "r"(b[1]));
}
__device__ __forceinline__ void cp_async16(uint32_t dst, const void* src) {
    asm volatile("cp.async.cg.shared.global [%0], [%1], 16;" :: "r"(dst), "l"(src));
}
__device__ __forceinline__ void cp_commit() {
    asm volatile("cp.async.commit_group;" ::: "memory");
}
__device__ __forceinline__ float fast_tanh(float x) {
    float y;
    asm("tanh.approx.f32 %0, %1;" : "=f"(y) : "f"(x));
    return y;
}

// ============================================================================
// SMEM layout for pass1 (dynamic) — occ 1, M=128 (R10/R13-proven config)
// ============================================================================
// x resident tile: 128 rows x 1024B (512 bf16), XOR-swizzled at 16B granule
#define OFF_XT   0
#define XT_BYTES (128 * 1024)            // 131072
// W chunk TRIPLE buffer: 128 n-rows x 144B (64 bf16 + 8 pad)
#define OFF_W0   XT_BYTES
#define W_ROWB   144
#define W_BUF    (128 * W_ROWB)          // 18432
// fp32 x staging: 128 rows x 64 floats = 32KB (single buffer, distance-1)
#define OFF_STG  (OFF_W0 + 3 * W_BUF)    // 186368
#define STG_BYTES 32768
#define OFF_B    (OFF_STG + STG_BYTES)   // 219136
#define OFF_U    (OFF_B + 2048)          // 221184
#define OFF_VU   (OFF_U + 2048)          // 223232 (128 floats)
#define OFF_RED  (OFF_VU + 512)          // 223744 (reduction scratch)
#define OFF_SW   (OFF_RED + 128)         // 223872 (128 softmax weights)
#define SMEM_TOTAL (OFF_SW + 512)        // 224384

// swizzled x address for (row, k-element)
__device__ __forceinline__ uint32_t xt_addr(uint32_t sb, int row, int k) {
    uint32_t unit = ((uint32_t)k >> 3) ^ ((uint32_t)row & 7);
    return sb + OFF_XT + (uint32_t)row * 1024 + (unit << 4) + (((uint32_t)k * 2) & 15);
}

// ============================================================================
// Kernel 0: W transpose + bf16 convert via SMEM-tiled transpose.
// 32x32 tiles -> 256 blocks, coalesced both directions.
// ============================================================================
__global__ void wprep_kernel(const float* __restrict__ w) {
    __shared__ __nv_bfloat16 t[32][33];          // +1 pad: conflict-free
    const int bh = (blockIdx.x >> 4) * 32;       // h tile origin (16 tiles)
    const int ba = (blockIdx.x & 15) * 32;       // a tile origin (16 tiles)
    #pragma unroll
    for (int i = 0; i < 4; i++) {
        const int idx = i * 256 + threadIdx.x;   // 0..1023
        const int h = idx >> 5, a = idx & 31;    // read coalesced in a
        t[a][h] = __float2bfloat16(w[(size_t)(bh + h) * An + ba + a]);
    }
    __syncthreads();
    #pragma unroll
    for (int i = 0; i < 4; i++) {
        const int idx = i * 256 + threadIdx.x;
        const int a = idx >> 5, h = idx & 31;    // write coalesced in h
        g_wt[(size_t)(ba + a) * Hn + bh + h] = t[a][h];
    }
}

// ============================================================================
// Prefetch helpers — each ALWAYS commits a group (uniform accounting).
// 512 threads.
// ============================================================================
__device__ __forceinline__ void prefetch_W(uint32_t sb, int jt, int tid) {
    if (jt < NITER) {
        const int nn = jt >> 3, nk = jt & 7;
        const uint32_t dbase = sb + OFF_W0 + (jt % 3) * W_BUF;
        const int idx0 = tid * 2;
        #pragma unroll
        for (int i = 0; i < 2; i++) {
            const int idx = idx0 + i;                 // 1024 16B units
            const int r = idx >> 3, un = idx & 7;
            const __nv_bfloat16* src =
                g_wt + (size_t)(nn * NC + r) * Hn + nk * KC + un * 8;
            cp_async16(dbase + r * W_ROWB + un * 16, src);
        }
    }
    cp_commit();
}

__device__ __forceinline__ void prefetch_X(uint32_t sb, const float* __restrict__ x,
                                           size_t row0, int kc, int tid) {
    if (kc < NKC) {
        #pragma unroll
        for (int i = 0; i < 4; i++) {
            const int idx = tid + i * THREADS;        // 2048 16B units
            const int r = idx >> 4, un = idx & 15;    // row, float4-index
            const float* src = x + (row0 + r) * Hn + kc * KC + un * 4;
            cp_async16(sb + OFF_STG + r * 256 + un * 16, src);
        }
    }
    cp_commit();
}

// ============================================================================
// Kernel 1: fused GEMM(tanh, u-dot) -> g_vu, then per-tile local softmax
// weights + fp32 partial pooling.  512 threads (16 warps: 4x4 warp tiling).
// (R13 structure byte-for-byte; conversion loop upgraded to STS.128.)
// ============================================================================
__global__ void __launch_bounds__(THREADS, 1)
pass1_kernel(const float* __restrict__ x, const float* __restrict__ bo,
             const float* __restrict__ uo) {
    extern __shared__ char smem[];
    const uint32_t sb = smem_to_u32(smem);
    const int tid = threadIdx.x;
    const int lane = tid & 31;
    const int wid = tid >> 5;
    const int warp_m = wid & 3;           // 4 m-tiles of 32 rows
    const int warp_n = wid >> 2;          // 4 n-tiles of 32 cols
    const size_t row0 = (size_t)blockIdx.x * M_TILE;

    float* s_b   = (float*)(smem + OFF_B);
    float* s_u   = (float*)(smem + OFF_U);
    float* s_vu  = (float*)(smem + OFF_VU);
    float* s_red = (float*)(smem + OFF_RED);
    float* s_w   = (float*)(smem + OFF_SW);
    const float inv_sqrtA = 0.04419417382415922f;   // 1/sqrt(512)
    for (int i = tid; i < An; i += THREADS) {
        s_b[i] = bo[i];
        s_u[i] = uo[i] * inv_sqrtA;
    }
    if (tid < 128) s_vu[tid] = 0.0f;

    // Prologue groups (order matters): W0, X0, W1  -> pending before iter 0.
    prefetch_W(sb, 0, tid);
    prefetch_X(sb, x, row0, 0, tid);
    prefetch_W(sb, 1, tid);

    float acc[2][4][4];

    #pragma unroll 1
    for (int it = 0; it < NITER; it++) {
        const int nc = it >> 3;
        const int kc = it & 7;

        // Guarantees W(it) and X(it) have landed (newest group may be pending).
        asm volatile("cp.async.wait_group 1;" ::: "memory");
        __syncthreads();

        if (nc == 0) {
            // convert staged fp32 chunk kc -> swizzled bf16 resident tile.
            // STS.128: each thread converts 8 floats -> one 16B swizzled unit.
            #pragma unroll
            for (int i = 0; i < 2; i++) {
                const int idx = tid + i * THREADS;    // 1024 16B-dest units
                const int r = idx >> 3;               // row
                const int un = idx & 7;               // 16B unit within chunk
                const float4 v0 = *(const float4*)(smem + OFF_STG + r * 256 + un * 32);
                const float4 v1 = *(const float4*)(smem + OFF_STG + r * 256 + un * 32 + 16);
                __nv_bfloat162 p0 = __floats2bfloat162_rn(v0.x, v0.y);
                __nv_bfloat162 p1 = __floats2bfloat162_rn(v0.z, v0.w);
                __nv_bfloat162 p2 = __floats2bfloat162_rn(v1.x, v1.y);
                __nv_bfloat162 p3 = __floats2bfloat162_rn(v1.z, v1.w);
                uint4 st;
                st.x = *reinterpret_cast<const uint32_t*>(&p0);
                st.y = *reinterpret_cast<const uint32_t*>(&p1);
                st.z = *reinterpret_cast<const uint32_t*>(&p2);
                st.w = *reinterpret_cast<const uint32_t*>(&p3);
                const int k = kc * KC + un * 8;
                *(uint4*)(smem + (xt_addr(sb, r, k) - sb)) = st;
            }
            __syncthreads();   // converted data visible before ldmatrix reads it
        }

        // Issue next prefetches AFTER the barrier (race-free buffer reuse).
        prefetch_X(sb, x, row0, (nc == 0) ? (kc + 1) : NKC, tid);
        prefetch_W(sb, it + 2, tid);

        if (kc == 0) {
            #pragma unroll
            for (int mi = 0; mi < 2; mi++)
                #pragma unroll
                for (int ni = 0; ni < 4; ni++)
                    #pragma unroll
                    for (int j = 0; j < 4; j++) acc[mi][ni][j] = 0.0f;
        }

        // ---- compute this (nc, kc) chunk: 4 k-steps of 16 ----
        const uint32_t wb = sb + OFF_W0 + (it % 3) * W_BUF;
        #pragma unroll
        for (int ks = 0; ks < 4; ks++) {
            uint32_t afr[2][4];
            #pragma unroll
            for (int mi = 0; mi < 2; mi++) {
                const int row = warp_m * 32 + mi * 16 + (lane & 15);
                const int k = kc * KC + ks * 16 + (lane >> 4) * 8;
                ldsm_x4(xt_addr(sb, row, k), afr[mi]);
            }
            uint32_t bfr[4][2];
            #pragma unroll
            for (int g = 0; g < 2; g++) {
                const int n = warp_n * 32 + g * 16 + (lane & 15);
                uint32_t r4[4];
                ldsm_x4(wb + n * W_ROWB + ks * 32 + (lane >> 4) * 16, r4);
                bfr[2 * g][0] = r4[0]; bfr[2 * g][1] = r4[2];
                bfr[2 * g + 1][0] = r4[1]; bfr[2 * g + 1][1] = r4[3];
            }
            #pragma unroll
            for (int mi = 0; mi < 2; mi++)
                #pragma unroll
                for (int ni = 0; ni < 4; ni++)
                    mma16816(acc[mi][ni], afr[mi], bfr[ni]);
        }

        // ---- epilogue after full K sweep for this N-chunk ----
        if (kc == 7) {
            float pv[4] = {0.f, 0.f, 0.f, 0.f};   // [mi*2 + hi]
            #pragma unroll
            for (int mi = 0; mi < 2; mi++) {
                #pragma unroll
                for (int ni = 0; ni < 4; ni++) {
                    const int a0 = nc * NC + warp_n * 32 + ni * 8 + (lane & 3) * 2;
                    const float b0 = s_b[a0],     b1 = s_b[a0 + 1];
                    const float u0 = s_u[a0],     u1 = s_u[a0 + 1];
                    pv[mi * 2 + 0] += fast_tanh(acc[mi][ni][0] + b0) * u0
                                    + fast_tanh(acc[mi][ni][1] + b1) * u1;
                    pv[mi * 2 + 1] += fast_tanh(acc[mi][ni][2] + b0) * u0
                                    + fast_tanh(acc[mi][ni][3] + b1) * u1;
                }
            }
            #pragma unroll
            for (int j = 0; j < 4; j++) {
                float v = pv[j];
                v += __shfl_xor_sync(0xffffffffu, v, 1);
                v += __shfl_xor_sync(0xffffffffu, v, 2);
                if ((lane & 3) == 0) {
                    const int row = warp_m * 32 + (j >> 1) * 16 + (lane >> 2) + (j & 1) * 8;
                    atomicAdd(&s_vu[row], v);
                }
            }
        }
    }

    __syncthreads();
    if (tid < 128) g_vu[row0 + tid] = s_vu[tid];

    // ============== local softmax weights + fp32 partial pooling ==========
    if (wid == 0) {
        float a0 = fmaxf(s_vu[lane], s_vu[lane + 32]);
        float a1 = fmaxf(s_vu[lane + 64], s_vu[lane + 96]);
        float m = fmaxf(a0, a1);
        #pragma unroll
        for (int off = 16; off > 0; off >>= 1)
            m = fmaxf(m, __shfl_xor_sync(0xffffffffu, m, off));
        if (lane == 0) s_red[0] = m;
    }
    __syncthreads();
    const float lm = s_red[0];

    if (tid < 128) {
        const float w = expf(s_vu[tid] - lm);
        s_w[tid] = w;
        float sw = w;
        #pragma unroll
        for (int off = 16; off > 0; off >>= 1)
            sw += __shfl_xor_sync(0xffffffffu, sw, off);
        if (lane == 0) s_red[1 + wid] = sw;
    }
    __syncthreads();

    // partial pooled vector: P[h] = sum_r w_r * x[r][h] (fp32, direct LDG)
    // 512 threads: one column each. MLP=32 batches, 4 accumulators.
    const float* xb = x + row0 * Hn + tid;
    float a0 = 0.f, a1 = 0.f, a2 = 0.f, a3 = 0.f;
    #pragma unroll 1
    for (int rb = 0; rb < 128; rb += 32) {
        float v[32];
        #pragma unroll
        for (int i = 0; i < 32; i++)
            v[i] = xb[(size_t)(rb + i) * Hn];
        #pragma unroll
        for (int i = 0; i < 32; i += 4) {
            a0 = fmaf(s_w[rb + i + 0], v[i + 0], a0);
            a1 = fmaf(s_w[rb + i + 1], v[i + 1], a1);
            a2 = fmaf(s_w[rb + i + 2], v[i + 2], a2);
            a3 = fmaf(s_w[rb + i + 3], v[i + 3], a3);
        }
    }
    g_part[(size_t)blockIdx.x * Hn + tid] = (a0 + a1) + (a2 + a3);
    if (tid == 0) {
        g_m[blockIdx.x] = lm;
        g_s[blockIdx.x] = s_red[1] + s_red[2] + s_red[3] + s_red[4];
    }
}

// ============================================================================
// Kernel 2 (merged tail): per-batch softmax -> alphas + combine -> out.
// ============================================================================
__global__ void __launch_bounds__(512)
finish_kernel(float* __restrict__ out, float* __restrict__ alphas) {
    const int b = blockIdx.x;
    const int tid = threadIdx.x;
    const int w = tid >> 5, l = tid & 31;
    const float* vu = g_vu + (size_t)b * Sn;

    __shared__ float redm[16];
    __shared__ float reds[16];
    __shared__ float scoef[16];
    __shared__ float sZ;

    // ---- softmax over S=2048 (4 values/thread) ----
    float v[4];
    #pragma unroll
    for (int j = 0; j < 4; j++) v[j] = vu[tid + j * 512];

    float m = fmaxf(fmaxf(v[0], v[1]), fmaxf(v[2], v[3]));
    #pragma unroll
    for (int off = 16; off > 0; off >>= 1)
        m = fmaxf(m, __shfl_xor_sync(0xffffffffu, m, off));
    if (l == 0) redm[w] = m;
    __syncthreads();
    float gm = redm[0];
    #pragma unroll
    for (int i = 1; i < 16; i++) gm = fmaxf(gm, redm[i]);

    float e[4];
    float s = 0.0f;
    #pragma unroll
    for (int j = 0; j < 4; j++) { e[j] = expf(v[j] - gm); s += e[j]; }
    #pragma unroll
    for (int off = 16; off > 0; off >>= 1)
        s += __shfl_xor_sync(0xffffffffu, s, off);
    if (l == 0) reds[w] = s;

    // ---- combine coefficients (independent of softmax reductions) ----
    if (tid == 256) {
        float mm[16], ss[16];
        #pragma unroll
        for (int i = 0; i < 16; i++) { mm[i] = g_m[b * 16 + i]; ss[i] = g_s[b * 16 + i]; }
        float M = mm[0];
        #pragma unroll
        for (int i = 1; i < 16; i++) M = fmaxf(M, mm[i]);
        float Z = 0.0f;
        #pragma unroll
        for (int i = 0; i < 16; i++) {
            const float c = expf(mm[i] - M);
            scoef[i] = c;
            Z += c * ss[i];
        }
        sZ = Z + 1e-10f;
    }
    __syncthreads();

    float gs = 0.0f;
    #pragma unroll
    for (int i = 0; i < 16; i++) gs += reds[i];
    const float inv = 1.0f / (gs + 1e-10f);

    float* ao = alphas + (size_t)b * Sn;
    #pragma unroll
    for (int j = 0; j < 4; j++) ao[tid + j * 512] = e[j] * inv;

    // ---- combine: out[b][h] ----
    float acc = 0.0f;
    const float* pp = g_part + (size_t)b * 16 * Hn + tid;
    #pragma unroll
    for (int i = 0; i < 16; i++)
        acc = fmaf(scoef[i], pp[(size_t)i * Hn], acc);
    out[(size_t)b * Hn + tid] = acc / sZ;
}

// ============================================================================
// Launch
// ============================================================================
extern "C" void kernel_launch(void* const* d_in, const int* in_sizes, int n_in,
                              void* d_out, int out_size) {
    const float* x  = (const float*)d_in[0];   // [B,S,H]
    const float* w  = (const float*)d_in[1];   // [H,A]
    const float* bo = (const float*)d_in[2];   // [A]
    const float* uo = (const float*)d_in[3];   // [A]
    float* out = (float*)d_out;                // [B*H] output then [B*S] alphas
    float* alphas = out + (size_t)Bn * Hn;

    cudaFuncSetAttribute(pass1_kernel, cudaFuncAttributeMaxDynamicSharedMemorySize,
                         SMEM_TOTAL);

    wprep_kernel<<<256, 256>>>(w);
    pass1_kernel<<<N_TILES, THREADS, SMEM_TOTAL>>>(x, bo, uo);
    finish_kernel<<<Bn, 512>>>(out, alphas);
}

// round 16
// speedup vs baseline: 1.5403x; 1.0265x over previous
#include <cuda_runtime.h>
#include <cuda_bf16.h>
#include <cstdint>

// ============================================================================
// Problem constants
// ============================================================================
#define Bn 128
#define Sn 2048
#define Hn 512
#define An 512
#define BSn (Bn * Sn)            // 262144 rows
#define M_TILE 128
#define N_TILES (BSn / M_TILE)   // 2048 CTAs (16 per batch)
#define KC 64                    // K per chunk
#define NC 128                   // N per chunk
#define NKC (Hn / KC)            // 8
#define NNC (An / NC)            // 4
#define NITER (NKC * NNC)        // 32
#define THREADS 512

// ============================================================================
// Device scratch
// ============================================================================
__device__ float g_vu[BSn];                       // 1 MB
__device__ __nv_bfloat16 g_wt[An * Hn];           // 512 KB, Wt[a][h] = W[h][a]
__device__ float g_part[N_TILES * Hn];            // 4 MB partial pooled vectors
__device__ float g_m[N_TILES];                    // per-tile local max
__device__ float g_s[N_TILES];                    // per-tile local expsum

// ============================================================================
// Helpers (baseline PTX only — no 'a'-suffix features)
// ============================================================================
__device__ __forceinline__ uint32_t smem_to_u32(const void* p) {
    uint32_t a;
    asm("{ .reg .u64 t; cvta.to.shared.u64 t, %1; cvt.u32.u64 %0, t; }" : "=r"(a) : "l"(p));
    return a;
}
__device__ __forceinline__ void ldsm_x4(uint32_t addr, uint32_t r[4]) {
    asm volatile("ldmatrix.sync.aligned.m8n8.x4.shared.b16 {%0,%1,%2,%3}, [%4];"
        : "=r"(r[0]), "=r"(r[1]), "=r"(r[2]), "=r"(r[3]) : "r"(addr));
}
__device__ __forceinline__ void mma16816(float d[4], const uint32_t a[4],
                                         const uint32_t b[2]) {
    asm volatile("mma.sync.aligned.m16n8k16.row.col.f32.bf16.bf16.f32 "
        "{%0,%1,%2,%3}, {%4,%5,%6,%7}, {%8,%9}, {%0,%1,%2,%3};"
        : "+f"(d[0]), "+f"(d[1]), "+f"(d[2]), "+f"(d[3])
        : "r"(a[0]), "r"(a[1]), "r"(a[2]), "r"(a[3]), "r"(b[0]), "r"(b[1]));
}
__device__ __forceinline__ void cp_async16(uint32_t dst, const void* src) {
    asm volatile("cp.async.cg.shared.global [%0], [%1], 16;" :: "r"(dst), "l"(src));
}
__device__ __forceinline__ void cp_commit() {
    asm volatile("cp.async.commit_group;" ::: "memory");
}
__device__ __forceinline__ float fast_tanh(float x) {
    float y;
    asm("tanh.approx.f32 %0, %1;" : "=f"(y) : "f"(x));
    return y;
}

// ============================================================================
// SMEM layout for pass1 (dynamic) — occ 1, M=128 (R13-proven config)
// ============================================================================
// x resident tile: 128 rows x 1024B (512 bf16), XOR-swizzled at 16B granule
#define OFF_XT   0
#define XT_BYTES (128 * 1024)            // 131072
// W chunk TRIPLE buffer: 128 n-rows x 144B (64 bf16 + 8 pad)
#define OFF_W0   XT_BYTES
#define W_ROWB   144
#define W_BUF    (128 * W_ROWB)          // 18432
// fp32 x staging: 128 rows x 64 floats = 32KB (single buffer, distance-1)
#define OFF_STG  (OFF_W0 + 3 * W_BUF)    // 186368
#define STG_BYTES 32768
#define OFF_BU   (OFF_STG + STG_BYTES)   // 219136 : 512 float2 (b, u/sqrtA)
#define OFF_VU   (OFF_BU + 4096)         // 223232 (128 floats)
#define OFF_RED  (OFF_VU + 512)          // 223744 (reduction scratch)
#define OFF_SW   (OFF_RED + 128)         // 223872 (128 softmax weights)
#define SMEM_TOTAL (OFF_SW + 512)        // 224384

// swizzled x address for (row, k-element)
__device__ __forceinline__ uint32_t xt_addr(uint32_t sb, int row, int k) {
    uint32_t unit = ((uint32_t)k >> 3) ^ ((uint32_t)row & 7);
    return sb + OFF_XT + (uint32_t)row * 1024 + (unit << 4) + (((uint32_t)k * 2) & 15);
}

// ============================================================================
// Kernel 0: W transpose + bf16 convert via SMEM-tiled transpose.
// 32x32 tiles -> 256 blocks, coalesced both directions.
// ============================================================================
__global__ void wprep_kernel(const float* __restrict__ w) {
    __shared__ __nv_bfloat16 t[32][33];          // +1 pad: conflict-free
    const int bh = (blockIdx.x >> 4) * 32;       // h tile origin (16 tiles)
    const int ba = (blockIdx.x & 15) * 32;       // a tile origin (16 tiles)
    #pragma unroll
    for (int i = 0; i < 4; i++) {
        const int idx = i * 256 + threadIdx.x;   // 0..1023
        const int h = idx >> 5, a = idx & 31;    // read coalesced in a
        t[a][h] = __float2bfloat16(w[(size_t)(bh + h) * An + ba + a]);
    }
    __syncthreads();
    #pragma unroll
    for (int i = 0; i < 4; i++) {
        const int idx = i * 256 + threadIdx.x;
        const int a = idx >> 5, h = idx & 31;    // write coalesced in h
        g_wt[(size_t)(ba + a) * Hn + bh + h] = t[a][h];
    }
}

// ============================================================================
// Prefetch helpers — each ALWAYS commits a group (uniform accounting).
// 512 threads.
// ============================================================================
__device__ __forceinline__ void prefetch_W(uint32_t sb, int jt, int tid) {
    if (jt < NITER) {
        const int nn = jt >> 3, nk = jt & 7;
        const uint32_t dbase = sb + OFF_W0 + (jt % 3) * W_BUF;
        const int idx0 = tid * 2;
        #pragma unroll
        for (int i = 0; i < 2; i++) {
            const int idx = idx0 + i;                 // 1024 16B units
            const int r = idx >> 3, un = idx & 7;
            const __nv_bfloat16* src =
                g_wt + (size_t)(nn * NC + r) * Hn + nk * KC + un * 8;
            cp_async16(dbase + r * W_ROWB + un * 16, src);
        }
    }
    cp_commit();
}

__device__ __forceinline__ void prefetch_X(uint32_t sb, const float* __restrict__ x,
                                           size_t row0, int kc, int tid) {
    if (kc < NKC) {
        #pragma unroll
        for (int i = 0; i < 4; i++) {
            const int idx = tid + i * THREADS;        // 2048 16B units
            const int r = idx >> 4, un = idx & 15;    // row, float4-index
            const float* src = x + (row0 + r) * Hn + kc * KC + un * 4;
            cp_async16(sb + OFF_STG + r * 256 + un * 16, src);
        }
    }
    cp_commit();
}

// ============================================================================
// Kernel 1: fused GEMM(tanh, u-dot) -> g_vu, then per-tile local softmax
// weights + fp32 partial pooling.  512 threads (16 warps: 4x4 warp tiling).
// (R13 pass1 structure byte-for-byte; epilogue b/u reads packed as float4.)
// ============================================================================
__global__ void __launch_bounds__(THREADS, 1)
pass1_kernel(const float* __restrict__ x, const float* __restrict__ bo,
             const float* __restrict__ uo) {
    extern __shared__ char smem[];
    const uint32_t sb = smem_to_u32(smem);
    const int tid = threadIdx.x;
    const int lane = tid & 31;
    const int wid = tid >> 5;
    const int warp_m = wid & 3;           // 4 m-tiles of 32 rows
    const int warp_n = wid >> 2;          // 4 n-tiles of 32 cols
    const size_t row0 = (size_t)blockIdx.x * M_TILE;

    float2* s_bu = (float2*)(smem + OFF_BU);
    float* s_vu  = (float*)(smem + OFF_VU);
    float* s_red = (float*)(smem + OFF_RED);
    float* s_w   = (float*)(smem + OFF_SW);
    const float inv_sqrtA = 0.04419417382415922f;   // 1/sqrt(512)
    for (int i = tid; i < An; i += THREADS)
        s_bu[i] = make_float2(bo[i], uo[i] * inv_sqrtA);
    if (tid < 128) s_vu[tid] = 0.0f;

    // Prologue groups (order matters): W0, X0, W1  -> pending before iter 0.
    prefetch_W(sb, 0, tid);
    prefetch_X(sb, x, row0, 0, tid);
    prefetch_W(sb, 1, tid);

    float acc[2][4][4];

    #pragma unroll 1
    for (int it = 0; it < NITER; it++) {
        const int nc = it >> 3;
        const int kc = it & 7;

        // Guarantees W(it) and X(it) have landed (newest group may be pending).
        asm volatile("cp.async.wait_group 1;" ::: "memory");
        __syncthreads();

        if (nc == 0) {
            // convert staged fp32 chunk kc -> swizzled bf16 resident tile
            #pragma unroll
            for (int i = 0; i < 4; i++) {
                const int idx = tid + i * THREADS;
                const int r = idx >> 4;
                const int c4 = idx & 15;
                const float4 v = *(const float4*)(smem + OFF_STG + r * 256 + c4 * 16);
                __nv_bfloat162 p0 = __floats2bfloat162_rn(v.x, v.y);
                __nv_bfloat162 p1 = __floats2bfloat162_rn(v.z, v.w);
                uint2 st;
                st.x = *reinterpret_cast<const uint32_t*>(&p0);
                st.y = *reinterpret_cast<const uint32_t*>(&p1);
                const int k = kc * KC + c4 * 4;
                *(uint2*)(smem + (xt_addr(sb, r, k) - sb)) = st;
            }
            __syncthreads();   // converted data visible before ldmatrix reads it
        }

        // Issue next prefetches AFTER the barrier (race-free buffer reuse).
        prefetch_X(sb, x, row0, (nc == 0) ? (kc + 1) : NKC, tid);
        prefetch_W(sb, it + 2, tid);

        if (kc == 0) {
            #pragma unroll
            for (int mi = 0; mi < 2; mi++)
                #pragma unroll
                for (int ni = 0; ni < 4; ni++)
                    #pragma unroll
                    for (int j = 0; j < 4; j++) acc[mi][ni][j] = 0.0f;
        }

        // ---- compute this (nc, kc) chunk: 4 k-steps of 16 ----
        const uint32_t wb = sb + OFF_W0 + (it % 3) * W_BUF;
        #pragma unroll
        for (int ks = 0; ks < 4; ks++) {
            uint32_t afr[2][4];
            #pragma unroll
            for (int mi = 0; mi < 2; mi++) {
                const int row = warp_m * 32 + mi * 16 + (lane & 15);
                const int k = kc * KC + ks * 16 + (lane >> 4) * 8;
                ldsm_x4(xt_addr(sb, row, k), afr[mi]);
            }
            uint32_t bfr[4][2];
            #pragma unroll
            for (int g = 0; g < 2; g++) {
                const int n = warp_n * 32 + g * 16 + (lane & 15);
                uint32_t r4[4];
                ldsm_x4(wb + n * W_ROWB + ks * 32 + (lane >> 4) * 16, r4);
                bfr[2 * g][0] = r4[0]; bfr[2 * g][1] = r4[2];
                bfr[2 * g + 1][0] = r4[1]; bfr[2 * g + 1][1] = r4[3];
            }
            #pragma unroll
            for (int mi = 0; mi < 2; mi++)
                #pragma unroll
                for (int ni = 0; ni < 4; ni++)
                    mma16816(acc[mi][ni], afr[mi], bfr[ni]);
        }

        // ---- epilogue after full K sweep for this N-chunk ----
        if (kc == 7) {
            float pv[4] = {0.f, 0.f, 0.f, 0.f};   // [mi*2 + hi]
            #pragma unroll
            for (int ni = 0; ni < 4; ni++) {
                const int a0 = nc * NC + warp_n * 32 + ni * 8 + (lane & 3) * 2;
                // packed (b0,u0,b1,u1) — a0 even => 16B-aligned LDS.128
                const float4 bu = *(const float4*)(s_bu + a0);
                #pragma unroll
                for (int mi = 0; mi < 2; mi++) {
                    pv[mi * 2 + 0] += fast_tanh(acc[mi][ni][0] + bu.x) * bu.y
                                    + fast_tanh(acc[mi][ni][1] + bu.z) * bu.w;
                    pv[mi * 2 + 1] += fast_tanh(acc[mi][ni][2] + bu.x) * bu.y
                                    + fast_tanh(acc[mi][ni][3] + bu.z) * bu.w;
                }
            }
            #pragma unroll
            for (int j = 0; j < 4; j++) {
                float v = pv[j];
                v += __shfl_xor_sync(0xffffffffu, v, 1);
                v += __shfl_xor_sync(0xffffffffu, v, 2);
                if ((lane & 3) == 0) {
                    const int row = warp_m * 32 + (j >> 1) * 16 + (lane >> 2) + (j & 1) * 8;
                    atomicAdd(&s_vu[row], v);
                }
            }
        }
    }

    __syncthreads();
    if (tid < 128) g_vu[row0 + tid] = s_vu[tid];

    // ============== local softmax weights + fp32 partial pooling ==========
    if (wid == 0) {
        float a0 = fmaxf(s_vu[lane], s_vu[lane + 32]);
        float a1 = fmaxf(s_vu[lane + 64], s_vu[lane + 96]);
        float m = fmaxf(a0, a1);
        #pragma unroll
        for (int off = 16; off > 0; off >>= 1)
            m = fmaxf(m, __shfl_xor_sync(0xffffffffu, m, off));
        if (lane == 0) s_red[0] = m;
    }
    __syncthreads();
    const float lm = s_red[0];

    if (tid < 128) {
        const float w = expf(s_vu[tid] - lm);
        s_w[tid] = w;
        float sw = w;
        #pragma unroll
        for (int off = 16; off > 0; off >>= 1)
            sw += __shfl_xor_sync(0xffffffffu, sw, off);
        if (lane == 0) s_red[1 + wid] = sw;
    }
    __syncthreads();

    // partial pooled vector: P[h] = sum_r w_r * x[r][h] (fp32, direct LDG)
    // 512 threads: one column each. MLP=32 batches, 4 accumulators.
    const float* xb = x + row0 * Hn + tid;
    float a0 = 0.f, a1 = 0.f, a2 = 0.f, a3 = 0.f;
    #pragma unroll 1
    for (int rb = 0; rb < 128; rb += 32) {
        float v[32];
        #pragma unroll
        for (int i = 0; i < 32; i++)
            v[i] = xb[(size_t)(rb + i) * Hn];
        #pragma unroll
        for (int i = 0; i < 32; i += 4) {
            a0 = fmaf(s_w[rb + i + 0], v[i + 0], a0);
            a1 = fmaf(s_w[rb + i + 1], v[i + 1], a1);
            a2 = fmaf(s_w[rb + i + 2], v[i + 2], a2);
            a3 = fmaf(s_w[rb + i + 3], v[i + 3], a3);
        }
    }
    g_part[(size_t)blockIdx.x * Hn + tid] = (a0 + a1) + (a2 + a3);
    if (tid == 0) {
        g_m[blockIdx.x] = lm;
        g_s[blockIdx.x] = s_red[1] + s_red[2] + s_red[3] + s_red[4];
    }
}

// ============================================================================
// Kernel 2 (merged tail): per-batch softmax -> alphas + combine -> out.
// ============================================================================
__global__ void __launch_bounds__(512)
finish_kernel(float* __restrict__ out, float* __restrict__ alphas) {
    const int b = blockIdx.x;
    const int tid = threadIdx.x;
    const int w = tid >> 5, l = tid & 31;
    const float* vu = g_vu + (size_t)b * Sn;

    __shared__ float redm[16];
    __shared__ float reds[16];
    __shared__ float scoef[16];
    __shared__ float sZ;

    // ---- softmax over S=2048 (4 values/thread) ----
    float v[4];
    #pragma unroll
    for (int j = 0; j < 4; j++) v[j] = vu[tid + j * 512];

    float m = fmaxf(fmaxf(v[0], v[1]), fmaxf(v[2], v[3]));
    #pragma unroll
    for (int off = 16; off > 0; off >>= 1)
        m = fmaxf(m, __shfl_xor_sync(0xffffffffu, m, off));
    if (l == 0) redm[w] = m;
    __syncthreads();
    float gm = redm[0];
    #pragma unroll
    for (int i = 1; i < 16; i++) gm = fmaxf(gm, redm[i]);

    float e[4];
    float s = 0.0f;
    #pragma unroll
    for (int j = 0; j < 4; j++) { e[j] = expf(v[j] - gm); s += e[j]; }
    #pragma unroll
    for (int off = 16; off > 0; off >>= 1)
        s += __shfl_xor_sync(0xffffffffu, s, off);
    if (l == 0) reds[w] = s;

    // ---- combine coefficients (independent of softmax reductions) ----
    if (tid == 256) {
        float mm[16], ss[16];
        #pragma unroll
        for (int i = 0; i < 16; i++) { mm[i] = g_m[b * 16 + i]; ss[i] = g_s[b * 16 + i]; }
        float M = mm[0];
        #pragma unroll
        for (int i = 1; i < 16; i++) M = fmaxf(M, mm[i]);
        float Z = 0.0f;
        #pragma unroll
        for (int i = 0; i < 16; i++) {
            const float c = expf(mm[i] - M);
            scoef[i] = c;
            Z += c * ss[i];
        }
        sZ = Z + 1e-10f;
    }
    __syncthreads();

    float gs = 0.0f;
    #pragma unroll
    for (int i = 0; i < 16; i++) gs += reds[i];
    const float inv = 1.0f / (gs + 1e-10f);

    float* ao = alphas + (size_t)b * Sn;
    #pragma unroll
    for (int j = 0; j < 4; j++) ao[tid + j * 512] = e[j] * inv;

    // ---- combine: out[b][h] ----
    float acc = 0.0f;
    const float* pp = g_part + (size_t)b * 16 * Hn + tid;
    #pragma unroll
    for (int i = 0; i < 16; i++)
        acc = fmaf(scoef[i], pp[(size_t)i * Hn], acc);
    out[(size_t)b * Hn + tid] = acc / sZ;
}

// ============================================================================
// Launch
// ============================================================================
extern "C" void kernel_launch(void* const* d_in, const int* in_sizes, int n_in,
                              void* d_out, int out_size) {
    const float* x  = (const float*)d_in[0];   // [B,S,H]
    const float* w  = (const float*)d_in[1];   // [H,A]
    const float* bo = (const float*)d_in[2];   // [A]
    const float* uo = (const float*)d_in[3];   // [A]
    float* out = (float*)d_out;                // [B*H] output then [B*S] alphas
    float* alphas = out + (size_t)Bn * Hn;

    cudaFuncSetAttribute(pass1_kernel, cudaFuncAttributeMaxDynamicSharedMemorySize,
                         SMEM_TOTAL);

    wprep_kernel<<<256, 256>>>(w);
    pass1_kernel<<<N_TILES, THREADS, SMEM_TOTAL>>>(x, bo, uo);
    finish_kernel<<<Bn, 512>>>(out, alphas);
}

// round 17
// speedup vs baseline: 1.5644x; 1.0157x over previous
#include <cuda_runtime.h>
#include <cuda_bf16.h>
#include <cstdint>

// ============================================================================
// Problem constants
// ============================================================================
#define Bn 128
#define Sn 2048
#define Hn 512
#define An 512
#define BSn (Bn * Sn)            // 262144 rows
#define M_TILE 128
#define N_TILES (BSn / M_TILE)   // 2048 CTAs (16 per batch)
#define KC 64                    // K per chunk
#define NC 128                   // N per chunk
#define NKC (Hn / KC)            // 8
#define NNC (An / NC)            // 4
#define NITER (NKC * NNC)        // 32
#define THREADS 512

// ============================================================================
// Device scratch
// ============================================================================
__device__ float g_vu[BSn];                       // 1 MB
__device__ __nv_bfloat16 g_wt[An * Hn];           // 512 KB, Wt[a][h] = W[h][a]
__device__ float g_part[N_TILES * Hn];            // 4 MB partial pooled vectors
__device__ float g_m[N_TILES];                    // per-tile local max
__device__ float g_s[N_TILES];                    // per-tile local expsum

// ============================================================================
// Helpers (baseline PTX only — no 'a'-suffix features)
// ============================================================================
__device__ __forceinline__ uint32_t smem_to_u32(const void* p) {
    uint32_t a;
    asm("{ .reg .u64 t; cvta.to.shared.u64 t, %1; cvt.u32.u64 %0, t; }" : "=r"(a) : "l"(p));
    return a;
}
__device__ __forceinline__ void ldsm_x4(uint32_t addr, uint32_t r[4]) {
    asm volatile("ldmatrix.sync.aligned.m8n8.x4.shared.b16 {%0,%1,%2,%3}, [%4];"
        : "=r"(r[0]), "=r"(r[1]), "=r"(r[2]), "=r"(r[3]) : "r"(addr));
}
__device__ __forceinline__ void mma16816(float d[4], const uint32_t a[4],
                                         const uint32_t b[2]) {
    asm volatile("mma.sync.aligned.m16n8k16.row.col.f32.bf16.bf16.f32 "
        "{%0,%1,%2,%3}, {%4,%5,%6,%7}, {%8,%9}, {%0,%1,%2,%3};"
        : "+f"(d[0]), "+f"(d[1]), "+f"(d[2]), "+f"(d[3])
        : "r"(a[0]), "r"(a[1]), "r"(a[2]), "r"(a[3]), "r"(b[0]), "r"(b[1]));
}
__device__ __forceinline__ void cp_async16(uint32_t dst, const void* src) {
    asm volatile("cp.async.cg.shared.global [%0], [%1], 16;" :: "r"(dst), "l"(src));
}
__device__ __forceinline__ void cp_commit() {
    asm volatile("cp.async.commit_group;" ::: "memory");
}
__device__ __forceinline__ float fast_tanh(float x) {
    float y;
    asm("tanh.approx.f32 %0, %1;" : "=f"(y) : "f"(x));
    return y;
}

// ============================================================================
// SMEM layout for pass1 (dynamic) — occ 1, M=128 (R13/R16-proven config)
// ============================================================================
// x resident tile: 128 rows x 1024B (512 bf16), XOR-swizzled at 16B granule
#define OFF_XT   0
#define XT_BYTES (128 * 1024)            // 131072
// W chunk TRIPLE buffer: 128 n-rows x 144B (64 bf16 + 8 pad)
#define OFF_W0   XT_BYTES
#define W_ROWB   144
#define W_BUF    (128 * W_ROWB)          // 18432
// fp32 x staging: 128 rows x 64 floats = 32KB (single buffer, distance-1)
#define OFF_STG  (OFF_W0 + 3 * W_BUF)    // 186368
#define STG_BYTES 32768
#define OFF_BU   (OFF_STG + STG_BYTES)   // 219136 : 512 float2 (b, u/sqrtA)
#define OFF_VU4  (OFF_BU + 4096)         // 223232 : 4 banks x 128 floats
#define OFF_RED  (OFF_VU4 + 2048)        // 225280 (reduction scratch)
#define OFF_SW   (OFF_RED + 128)         // 225408 (128 softmax weights)
#define SMEM_TOTAL (OFF_SW + 512)        // 225920

// swizzled x address for (row, k-element)
__device__ __forceinline__ uint32_t xt_addr(uint32_t sb, int row, int k) {
    uint32_t unit = ((uint32_t)k >> 3) ^ ((uint32_t)row & 7);
    return sb + OFF_XT + (uint32_t)row * 1024 + (unit << 4) + (((uint32_t)k * 2) & 15);
}

// ============================================================================
// Kernel 0: W transpose + bf16 convert via SMEM-tiled transpose.
// 32x32 tiles -> 256 blocks, coalesced both directions.
// ============================================================================
__global__ void wprep_kernel(const float* __restrict__ w) {
    __shared__ __nv_bfloat16 t[32][33];          // +1 pad: conflict-free
    const int bh = (blockIdx.x >> 4) * 32;       // h tile origin (16 tiles)
    const int ba = (blockIdx.x & 15) * 32;       // a tile origin (16 tiles)
    #pragma unroll
    for (int i = 0; i < 4; i++) {
        const int idx = i * 256 + threadIdx.x;   // 0..1023
        const int h = idx >> 5, a = idx & 31;    // read coalesced in a
        t[a][h] = __float2bfloat16(w[(size_t)(bh + h) * An + ba + a]);
    }
    __syncthreads();
    #pragma unroll
    for (int i = 0; i < 4; i++) {
        const int idx = i * 256 + threadIdx.x;
        const int a = idx >> 5, h = idx & 31;    // write coalesced in h
        g_wt[(size_t)(ba + a) * Hn + bh + h] = t[a][h];
    }
}

// ============================================================================
// Prefetch helpers — each ALWAYS commits a group (uniform accounting).
// 512 threads.
// ============================================================================
__device__ __forceinline__ void prefetch_W(uint32_t sb, int jt, int tid) {
    if (jt < NITER) {
        const int nn = jt >> 3, nk = jt & 7;
        const uint32_t dbase = sb + OFF_W0 + (jt % 3) * W_BUF;
        const int idx0 = tid * 2;
        #pragma unroll
        for (int i = 0; i < 2; i++) {
            const int idx = idx0 + i;                 // 1024 16B units
            const int r = idx >> 3, un = idx & 7;
            const __nv_bfloat16* src =
                g_wt + (size_t)(nn * NC + r) * Hn + nk * KC + un * 8;
            cp_async16(dbase + r * W_ROWB + un * 16, src);
        }
    }
    cp_commit();
}

__device__ __forceinline__ void prefetch_X(uint32_t sb, const float* __restrict__ x,
                                           size_t row0, int kc, int tid) {
    if (kc < NKC) {
        #pragma unroll
        for (int i = 0; i < 4; i++) {
            const int idx = tid + i * THREADS;        // 2048 16B units
            const int r = idx >> 4, un = idx & 15;    // row, float4-index
            const float* src = x + (row0 + r) * Hn + kc * KC + un * 4;
            cp_async16(sb + OFF_STG + r * 256 + un * 16, src);
        }
    }
    cp_commit();
}

// ============================================================================
// Kernel 1: fused GEMM(tanh, u-dot) -> g_vu, then per-tile local softmax
// weights + fp32 partial pooling.  512 threads (16 warps: 4x4 warp tiling).
// (R16 pass1 stream byte-for-byte; epilogue atomics replaced by per-warp_n
// banks — each (bank,row) has exactly one writer thread across all N-chunks.)
// ============================================================================
__global__ void __launch_bounds__(THREADS, 1)
pass1_kernel(const float* __restrict__ x, const float* __restrict__ bo,
             const float* __restrict__ uo) {
    extern __shared__ char smem[];
    const uint32_t sb = smem_to_u32(smem);
    const int tid = threadIdx.x;
    const int lane = tid & 31;
    const int wid = tid >> 5;
    const int warp_m = wid & 3;           // 4 m-tiles of 32 rows
    const int warp_n = wid >> 2;          // 4 n-tiles of 32 cols
    const size_t row0 = (size_t)blockIdx.x * M_TILE;

    float2* s_bu  = (float2*)(smem + OFF_BU);
    float*  s_vu4 = (float*)(smem + OFF_VU4);   // [4 banks][128 rows]
    float*  s_red = (float*)(smem + OFF_RED);
    float*  s_w   = (float*)(smem + OFF_SW);
    const float inv_sqrtA = 0.04419417382415922f;   // 1/sqrt(512)
    for (int i = tid; i < An; i += THREADS)
        s_bu[i] = make_float2(bo[i], uo[i] * inv_sqrtA);
    s_vu4[tid] = 0.0f;                               // all 512 bank cells

    // Prologue groups (order matters): W0, X0, W1  -> pending before iter 0.
    prefetch_W(sb, 0, tid);
    prefetch_X(sb, x, row0, 0, tid);
    prefetch_W(sb, 1, tid);

    float acc[2][4][4];

    #pragma unroll 1
    for (int it = 0; it < NITER; it++) {
        const int nc = it >> 3;
        const int kc = it & 7;

        // Guarantees W(it) and X(it) have landed (newest group may be pending).
        asm volatile("cp.async.wait_group 1;" ::: "memory");
        __syncthreads();

        if (nc == 0) {
            // convert staged fp32 chunk kc -> swizzled bf16 resident tile
            #pragma unroll
            for (int i = 0; i < 4; i++) {
                const int idx = tid + i * THREADS;
                const int r = idx >> 4;
                const int c4 = idx & 15;
                const float4 v = *(const float4*)(smem + OFF_STG + r * 256 + c4 * 16);
                __nv_bfloat162 p0 = __floats2bfloat162_rn(v.x, v.y);
                __nv_bfloat162 p1 = __floats2bfloat162_rn(v.z, v.w);
                uint2 st;
                st.x = *reinterpret_cast<const uint32_t*>(&p0);
                st.y = *reinterpret_cast<const uint32_t*>(&p1);
                const int k = kc * KC + c4 * 4;
                *(uint2*)(smem + (xt_addr(sb, r, k) - sb)) = st;
            }
            __syncthreads();   // converted data visible before ldmatrix reads it
        }

        // Issue next prefetches AFTER the barrier (race-free buffer reuse).
        prefetch_X(sb, x, row0, (nc == 0) ? (kc + 1) : NKC, tid);
        prefetch_W(sb, it + 2, tid);

        if (kc == 0) {
            #pragma unroll
            for (int mi = 0; mi < 2; mi++)
                #pragma unroll
                for (int ni = 0; ni < 4; ni++)
                    #pragma unroll
                    for (int j = 0; j < 4; j++) acc[mi][ni][j] = 0.0f;
        }

        // ---- compute this (nc, kc) chunk: 4 k-steps of 16 ----
        const uint32_t wb = sb + OFF_W0 + (it % 3) * W_BUF;
        #pragma unroll
        for (int ks = 0; ks < 4; ks++) {
            uint32_t afr[2][4];
            #pragma unroll
            for (int mi = 0; mi < 2; mi++) {
                const int row = warp_m * 32 + mi * 16 + (lane & 15);
                const int k = kc * KC + ks * 16 + (lane >> 4) * 8;
                ldsm_x4(xt_addr(sb, row, k), afr[mi]);
            }
            uint32_t bfr[4][2];
            #pragma unroll
            for (int g = 0; g < 2; g++) {
                const int n = warp_n * 32 + g * 16 + (lane & 15);
                uint32_t r4[4];
                ldsm_x4(wb + n * W_ROWB + ks * 32 + (lane >> 4) * 16, r4);
                bfr[2 * g][0] = r4[0]; bfr[2 * g][1] = r4[2];
                bfr[2 * g + 1][0] = r4[1]; bfr[2 * g + 1][1] = r4[3];
            }
            #pragma unroll
            for (int mi = 0; mi < 2; mi++)
                #pragma unroll
                for (int ni = 0; ni < 4; ni++)
                    mma16816(acc[mi][ni], afr[mi], bfr[ni]);
        }

        // ---- epilogue after full K sweep for this N-chunk ----
        if (kc == 7) {
            float pv[4] = {0.f, 0.f, 0.f, 0.f};   // [mi*2 + hi]
            #pragma unroll
            for (int ni = 0; ni < 4; ni++) {
                const int a0 = nc * NC + warp_n * 32 + ni * 8 + (lane & 3) * 2;
                // packed (b0,u0,b1,u1) — a0 even => 16B-aligned LDS.128
                const float4 bu = *(const float4*)(s_bu + a0);
                #pragma unroll
                for (int mi = 0; mi < 2; mi++) {
                    pv[mi * 2 + 0] += fast_tanh(acc[mi][ni][0] + bu.x) * bu.y
                                    + fast_tanh(acc[mi][ni][1] + bu.z) * bu.w;
                    pv[mi * 2 + 1] += fast_tanh(acc[mi][ni][2] + bu.x) * bu.y
                                    + fast_tanh(acc[mi][ni][3] + bu.z) * bu.w;
                }
            }
            #pragma unroll
            for (int j = 0; j < 4; j++) {
                float v = pv[j];
                v += __shfl_xor_sync(0xffffffffu, v, 1);
                v += __shfl_xor_sync(0xffffffffu, v, 2);
                if ((lane & 3) == 0) {
                    const int row = warp_m * 32 + (j >> 1) * 16 + (lane >> 2) + (j & 1) * 8;
                    // one writer per (warp_n bank, row) across all nc: no race
                    s_vu4[warp_n * 128 + row] += v;
                }
            }
        }
    }

    __syncthreads();
    // Reduce the 4 banks -> final vu; store to gmem and into bank 0 for reuse.
    if (tid < 128) {
        const float t = (s_vu4[tid] + s_vu4[128 + tid])
                      + (s_vu4[256 + tid] + s_vu4[384 + tid]);
        g_vu[row0 + tid] = t;
        s_vu4[tid] = t;
    }
    __syncthreads();

    // ============== local softmax weights + fp32 partial pooling ==========
    if (wid == 0) {
        float a0 = fmaxf(s_vu4[lane], s_vu4[lane + 32]);
        float a1 = fmaxf(s_vu4[lane + 64], s_vu4[lane + 96]);
        float m = fmaxf(a0, a1);
        #pragma unroll
        for (int off = 16; off > 0; off >>= 1)
            m = fmaxf(m, __shfl_xor_sync(0xffffffffu, m, off));
        if (lane == 0) s_red[0] = m;
    }
    __syncthreads();
    const float lm = s_red[0];

    if (tid < 128) {
        const float w = expf(s_vu4[tid] - lm);
        s_w[tid] = w;
        float sw = w;
        #pragma unroll
        for (int off = 16; off > 0; off >>= 1)
            sw += __shfl_xor_sync(0xffffffffu, sw, off);
        if (lane == 0) s_red[1 + wid] = sw;
    }
    __syncthreads();

    // partial pooled vector: P[h] = sum_r w_r * x[r][h] (fp32, direct LDG)
    // 512 threads: one column each. MLP=32 batches, 4 accumulators.
    const float* xb = x + row0 * Hn + tid;
    float a0 = 0.f, a1 = 0.f, a2 = 0.f, a3 = 0.f;
    #pragma unroll 1
    for (int rb = 0; rb < 128; rb += 32) {
        float v[32];
        #pragma unroll
        for (int i = 0; i < 32; i++)
            v[i] = xb[(size_t)(rb + i) * Hn];
        #pragma unroll
        for (int i = 0; i < 32; i += 4) {
            a0 = fmaf(s_w[rb + i + 0], v[i + 0], a0);
            a1 = fmaf(s_w[rb + i + 1], v[i + 1], a1);
            a2 = fmaf(s_w[rb + i + 2], v[i + 2], a2);
            a3 = fmaf(s_w[rb + i + 3], v[i + 3], a3);
        }
    }
    g_part[(size_t)blockIdx.x * Hn + tid] = (a0 + a1) + (a2 + a3);
    if (tid == 0) {
        g_m[blockIdx.x] = lm;
        g_s[blockIdx.x] = s_red[1] + s_red[2] + s_red[3] + s_red[4];
    }
}

// ============================================================================
// Kernel 2 (merged tail): per-batch softmax -> alphas + combine -> out.
// ============================================================================
__global__ void __launch_bounds__(512)
finish_kernel(float* __restrict__ out, float* __restrict__ alphas) {
    const int b = blockIdx.x;
    const int tid = threadIdx.x;
    const int w = tid >> 5, l = tid & 31;
    const float* vu = g_vu + (size_t)b * Sn;

    __shared__ float redm[16];
    __shared__ float reds[16];
    __shared__ float scoef[16];
    __shared__ float sZ;

    // ---- softmax over S=2048 (4 values/thread) ----
    float v[4];
    #pragma unroll
    for (int j = 0; j < 4; j++) v[j] = vu[tid + j * 512];

    float m = fmaxf(fmaxf(v[0], v[1]), fmaxf(v[2], v[3]));
    #pragma unroll
    for (int off = 16; off > 0; off >>= 1)
        m = fmaxf(m, __shfl_xor_sync(0xffffffffu, m, off));
    if (l == 0) redm[w] = m;
    __syncthreads();
    float gm = redm[0];
    #pragma unroll
    for (int i = 1; i < 16; i++) gm = fmaxf(gm, redm[i]);

    float e[4];
    float s = 0.0f;
    #pragma unroll
    for (int j = 0; j < 4; j++) { e[j] = expf(v[j] - gm); s += e[j]; }
    #pragma unroll
    for (int off = 16; off > 0; off >>= 1)
        s += __shfl_xor_sync(0xffffffffu, s, off);
    if (l == 0) reds[w] = s;

    // ---- combine coefficients (independent of softmax reductions) ----
    if (tid == 256) {
        float mm[16], ss[16];
        #pragma unroll
        for (int i = 0; i < 16; i++) { mm[i] = g_m[b * 16 + i]; ss[i] = g_s[b * 16 + i]; }
        float M = mm[0];
        #pragma unroll
        for (int i = 1; i < 16; i++) M = fmaxf(M, mm[i]);
        float Z = 0.0f;
        #pragma unroll
        for (int i = 0; i < 16; i++) {
            const float c = expf(mm[i] - M);
            scoef[i] = c;
            Z += c * ss[i];
        }
        sZ = Z + 1e-10f;
    }
    __syncthreads();

    float gs = 0.0f;
    #pragma unroll
    for (int i = 0; i < 16; i++) gs += reds[i];
    const float inv = 1.0f / (gs + 1e-10f);

    float* ao = alphas + (size_t)b * Sn;
    #pragma unroll
    for (int j = 0; j < 4; j++) ao[tid + j * 512] = e[j] * inv;

    // ---- combine: out[b][h] ----
    float acc = 0.0f;
    const float* pp = g_part + (size_t)b * 16 * Hn + tid;
    #pragma unroll
    for (int i = 0; i < 16; i++)
        acc = fmaf(scoef[i], pp[(size_t)i * Hn], acc);
    out[(size_t)b * Hn + tid] = acc / sZ;
}

// ============================================================================
// Launch
// ============================================================================
extern "C" void kernel_launch(void* const* d_in, const int* in_sizes, int n_in,
                              void* d_out, int out_size) {
    const float* x  = (const float*)d_in[0];   // [B,S,H]
    const float* w  = (const float*)d_in[1];   // [H,A]
    const float* bo = (const float*)d_in[2];   // [A]
    const float* uo = (const float*)d_in[3];   // [A]
    float* out = (float*)d_out;                // [B*H] output then [B*S] alphas
    float* alphas = out + (size_t)Bn * Hn;

    cudaFuncSetAttribute(pass1_kernel, cudaFuncAttributeMaxDynamicSharedMemorySize,
                         SMEM_TOTAL);

    wprep_kernel<<<256, 256>>>(w);
    pass1_kernel<<<N_TILES, THREADS, SMEM_TOTAL>>>(x, bo, uo);
    finish_kernel<<<Bn, 512>>>(out, alphas);
}